// round 3
// baseline (speedup 1.0000x reference)
#include <cuda_runtime.h>
#include <cstdint>

// Problem constants: B=2, H=16, S=2048, D=64, temperature=8
#define S_LEN 2048
#define D_DIM 64
#define TQ    16        // q rows per CTA
#define CK    256       // key chunk
#define NTHREADS 256

__device__ __forceinline__ unsigned long long pk2(float a, float b) {
    unsigned long long r;
    asm("mov.b64 %0, {%1, %2};" : "=l"(r) : "f"(a), "f"(b));
    return r;
}
__device__ __forceinline__ unsigned long long f2fma(unsigned long long a,
                                                    unsigned long long b,
                                                    unsigned long long c) {
    unsigned long long d;
    asm("fma.rn.f32x2 %0, %1, %2, %3;" : "=l"(d) : "l"(a), "l"(b), "l"(c));
    return d;
}
__device__ __forceinline__ float2 upk2(unsigned long long a) {
    float lo, hi;
    asm("mov.b64 {%0, %1}, %2;" : "=f"(lo), "=f"(hi) : "l"(a));
    return make_float2(lo, hi);
}

__global__ __launch_bounds__(NTHREADS, 1)
void sdpa_kernel(const float* __restrict__ q, const float* __restrict__ k,
                 const float* __restrict__ v, const int* __restrict__ mask,
                 float* __restrict__ outp, float* __restrict__ attnp)
{
    extern __shared__ float smem[];
    float* Sbuf  = smem;                          // [TQ][S_LEN]  = 128 KB (exp values)
    float* Kt    = Sbuf + TQ * S_LEN;             // [D][CK] swizzled (also reused as Vs[CK][D])
    float* Qst   = Kt + D_DIM * CK;               // [D][TQ] transposed q
    float* Zs    = Qst + D_DIM * TQ;              // [TQ]
    float* invZs = Zs + TQ;                       // [TQ]

    const int tid = threadIdx.x;
    const int qt  = blockIdx.x;                   // 0..127 q-tile
    const int bh  = blockIdx.y;                   // 0..31  (b*16+h)
    const int b   = bh >> 4;
    const int q0  = qt * TQ;

    const float* qb = q + (size_t)bh * S_LEN * D_DIM;
    const float* kb = k + (size_t)bh * S_LEN * D_DIM;
    const float* vb = v + (size_t)bh * S_LEN * D_DIM;
    const int*   mb = mask + (size_t)b * S_LEN * S_LEN;

    // ---- load Q transposed: Qst[d][r]  (FIX: grid-stride over all TQ*D elems) ----
    #pragma unroll
    for (int idx = tid; idx < TQ * D_DIM; idx += NTHREADS) {
        int r = idx / D_DIM, d = idx % D_DIM;
        Qst[d * TQ + r] = qb[(size_t)(q0 + r) * D_DIM + d];
    }
    if (tid < TQ) Zs[tid] = 0.f;

    // ---- phase 1: QK^T + mask + exp -> Sbuf, partial Z in regs ----
    const int ty = tid >> 6;          // 0..3   (4 q rows each)
    const int tx = tid & 63;          // 0..63  (4 keys each per chunk)
    const int colbase = tx << 2;

    float zp[4] = {0.f, 0.f, 0.f, 0.f};

    for (int kbase = 0; kbase < S_LEN; kbase += CK) {
        __syncthreads();
        // load K chunk transposed with XOR swizzle: element (d,key) -> Kt[d*CK + (key ^ (d&60))]
        {
            const float4* kg4 = (const float4*)(kb + (size_t)kbase * D_DIM);
            #pragma unroll
            for (int t = 0; t < (CK * D_DIM / 4) / NTHREADS; ++t) {
                int idx = tid + t * NTHREADS;
                int key = idx >> 4, dg = idx & 15;
                float4 val = kg4[idx];
                int col = key ^ (dg << 2);
                Kt[(dg * 4 + 0) * CK + col] = val.x;
                Kt[(dg * 4 + 1) * CK + col] = val.y;
                Kt[(dg * 4 + 2) * CK + col] = val.z;
                Kt[(dg * 4 + 3) * CK + col] = val.w;
            }
        }
        __syncthreads();

        unsigned long long acc[4][2];
        #pragma unroll
        for (int i = 0; i < 4; ++i) { acc[i][0] = 0ull; acc[i][1] = 0ull; }

        #pragma unroll 8
        for (int d = 0; d < D_DIM; ++d) {
            int col = colbase ^ (d & 60);
            float4 kv = *(const float4*)&Kt[d * CK + col];
            unsigned long long k01 = pk2(kv.x, kv.y);
            unsigned long long k23 = pk2(kv.z, kv.w);
            float4 qv = *(const float4*)&Qst[d * TQ + (ty << 2)];
            unsigned long long qq;
            qq = pk2(qv.x, qv.x); acc[0][0] = f2fma(qq, k01, acc[0][0]); acc[0][1] = f2fma(qq, k23, acc[0][1]);
            qq = pk2(qv.y, qv.y); acc[1][0] = f2fma(qq, k01, acc[1][0]); acc[1][1] = f2fma(qq, k23, acc[1][1]);
            qq = pk2(qv.z, qv.z); acc[2][0] = f2fma(qq, k01, acc[2][0]); acc[2][1] = f2fma(qq, k23, acc[2][1]);
            qq = pk2(qv.w, qv.w); acc[3][0] = f2fma(qq, k01, acc[3][0]); acc[3][1] = f2fma(qq, k23, acc[3][1]);
        }

        // epilogue: mask + exp, write to Sbuf
        #pragma unroll
        for (int i = 0; i < 4; ++i) {
            int r = (ty << 2) + i;
            int gq = q0 + r;
            float2 a0 = upk2(acc[i][0]);
            float2 a1 = upk2(acc[i][1]);
            const int4 m = *(const int4*)(mb + (size_t)gq * S_LEN + kbase + colbase);
            float e0 = m.x ? __expf(a0.x * 0.125f) : 0.f;
            float e1 = m.y ? __expf(a0.y * 0.125f) : 0.f;
            float e2 = m.z ? __expf(a1.x * 0.125f) : 0.f;
            float e3 = m.w ? __expf(a1.y * 0.125f) : 0.f;
            zp[i] += (e0 + e1) + (e2 + e3);
            *(float4*)&Sbuf[r * S_LEN + kbase + colbase] = make_float4(e0, e1, e2, e3);
        }
    }

    // ---- Z reduction ----
    #pragma unroll
    for (int i = 0; i < 4; ++i) atomicAdd(&Zs[(ty << 2) + i], zp[i]);
    __syncthreads();
    if (tid < TQ) {
        float z = Zs[tid];
        invZs[tid] = (z > 0.f) ? (1.0f / z) : 0.f;
    }
    __syncthreads();

    // ---- phase 3: write normalized attn (coalesced float4) ----
    {
        float* attnb = attnp + (size_t)bh * S_LEN * S_LEN;
        #pragma unroll 1
        for (int r = 0; r < TQ; ++r) {
            float iz = invZs[r];
            float4* dst = (float4*)(attnb + (size_t)(q0 + r) * S_LEN);
            const float4* src = (const float4*)(Sbuf + r * S_LEN);
            #pragma unroll
            for (int c = tid; c < S_LEN / 4; c += NTHREADS) {
                float4 e = src[c];
                dst[c] = make_float4(e.x * iz, e.y * iz, e.z * iz, e.w * iz);
            }
        }
    }

    // ---- phase 4: PV (out[r][d] = sum_k e[r][k] * v[k][d]) ----
    const int tp  = tid & 31;          // dim pair: dims {2tp, 2tp+1}
    const int tg4 = (tid >> 5) & 3;    // rows tg4*4 .. tg4*4+3
    const int kk  = tid >> 7;          // key-parity split (4-key groups)

    unsigned long long oacc[4] = {0ull, 0ull, 0ull, 0ull};
    float* Vs = Kt;  // reuse K smem as Vs[CK][D]

    for (int kbase = 0; kbase < S_LEN; kbase += CK) {
        __syncthreads();
        {
            const float4* vg4 = (const float4*)(vb + (size_t)kbase * D_DIM);
            float4* Vs4 = (float4*)Vs;
            #pragma unroll
            for (int t = 0; t < (CK * D_DIM / 4) / NTHREADS; ++t)
                Vs4[tid + t * NTHREADS] = vg4[tid + t * NTHREADS];
        }
        __syncthreads();

        for (int kb0 = kk * 4; kb0 < CK; kb0 += 8) {
            float pf[4][4];
            #pragma unroll
            for (int i = 0; i < 4; ++i) {
                float4 p = *(const float4*)&Sbuf[((tg4 << 2) + i) * S_LEN + kbase + kb0];
                pf[i][0] = p.x; pf[i][1] = p.y; pf[i][2] = p.z; pf[i][3] = p.w;
            }
            #pragma unroll
            for (int m = 0; m < 4; ++m) {
                unsigned long long v2 =
                    *(const unsigned long long*)&Vs[(kb0 + m) * D_DIM + (tp << 1)];
                #pragma unroll
                for (int i = 0; i < 4; ++i)
                    oacc[i] = f2fma(pk2(pf[i][m], pf[i][m]), v2, oacc[i]);
            }
        }
    }

    // ---- combine the two key-parity halves and write output ----
    __syncthreads();
    float* scratch = Qst;   // 1024 floats, Q no longer needed
    if (kk == 1) {
        #pragma unroll
        for (int i = 0; i < 4; ++i) {
            float2 f = upk2(oacc[i]);
            int r = (tg4 << 2) + i;
            scratch[r * D_DIM + (tp << 1)]     = f.x;
            scratch[r * D_DIM + (tp << 1) + 1] = f.y;
        }
    }
    __syncthreads();
    if (kk == 0) {
        #pragma unroll
        for (int i = 0; i < 4; ++i) {
            float2 f = upk2(oacc[i]);
            int r = (tg4 << 2) + i;
            float iz = invZs[r];
            float2 o;
            o.x = (f.x + scratch[r * D_DIM + (tp << 1)])     * iz;
            o.y = (f.y + scratch[r * D_DIM + (tp << 1) + 1]) * iz;
            *(float2*)&outp[((size_t)bh * S_LEN + q0 + r) * D_DIM + (tp << 1)] = o;
        }
    }
}

extern "C" void kernel_launch(void* const* d_in, const int* in_sizes, int n_in,
                              void* d_out, int out_size)
{
    const float* q    = (const float*)d_in[0];
    const float* k    = (const float*)d_in[1];
    const float* v    = (const float*)d_in[2];
    const int*   mask = (const int*)d_in[3];

    float* outp  = (float*)d_out;
    float* attnp = outp + (size_t)2 * 16 * 2048 * 64;   // output first, then attn

    size_t smem_bytes = (size_t)(TQ * S_LEN + D_DIM * CK + D_DIM * TQ + 2 * TQ) * sizeof(float);
    cudaFuncSetAttribute(sdpa_kernel, cudaFuncAttributeMaxDynamicSharedMemorySize,
                         (int)smem_bytes);

    dim3 grid(S_LEN / TQ, 2 * 16);   // (128 q-tiles, 32 bh)
    sdpa_kernel<<<grid, NTHREADS, smem_bytes>>>(q, k, v, mask, outp, attnp);
}

// round 6
// speedup vs baseline: 2.4161x; 2.4161x over previous
#include <cuda_runtime.h>
#include <cuda_bf16.h>
#include <cstdint>

// B=2,H=16,S=2048,D=64, temp=8
#define S_LEN 2048
#define DD 64
#define CKK 128
#define NCH 16
#define NT 256

// K1 smem: Qhi,Qlo,Khi,Klo rows 128 x stride 144B ; Zs[128]
#define K1_QHI 0
#define K1_QLO 18432
#define K1_KHI 36864
#define K1_KLO 55296
#define K1_ZS  73728
#define K1_SMEM 74240
// K2 smem: Phi,Plo rows 128 x 272B ; Vhi,Vlo rows 128 x 144B ; IZ[128]
#define K2_PHI 0
#define K2_PLO 34816
#define K2_VHI 69632
#define K2_VLO 88064
#define K2_IZ  106496
#define K2_SMEM 107008

__device__ float zbuf_g[32 * 16 * 128];

static __device__ __forceinline__ uint32_t s2u(const void* p) {
    uint32_t a;
    asm("{ .reg .u64 t; cvta.to.shared.u64 t, %1; cvt.u32.u64 %0, t; }" : "=r"(a) : "l"(p));
    return a;
}
static __device__ __forceinline__ void pack2(float x, float y, uint32_t& h, uint32_t& l) {
    asm("cvt.rn.bf16x2.f32 %0, %1, %2;" : "=r"(h) : "f"(y), "f"(x));
    float hx = __uint_as_float(h << 16);
    float hy = __uint_as_float(h & 0xFFFF0000u);
    float lx = x - hx, ly = y - hy;
    asm("cvt.rn.bf16x2.f32 %0, %1, %2;" : "=r"(l) : "f"(ly), "f"(lx));
}
// exp(s) via exp2 poly, |rel err| ~2e-7, no MUFU
static __device__ __forceinline__ float fexp(float s) {
    float t = s * 1.4426950408889634f;
    float rn = t + 12582912.f;
    int n = __float_as_int(rn) - 0x4B400000;
    float f = t - (rn - 12582912.f);
    float r = 1.5403530393e-4f;
    r = fmaf(r, f, 1.3333558146e-3f);
    r = fmaf(r, f, 9.6181291076e-3f);
    r = fmaf(r, f, 5.5504108664e-2f);
    r = fmaf(r, f, 2.4022650696e-1f);
    r = fmaf(r, f, 6.9314718056e-1f);
    r = fmaf(r, f, 1.0f);
    return __int_as_float(__float_as_int(r) + (n << 23));
}
#define LDSM4(r0,r1,r2,r3,addr) \
    asm volatile("ldmatrix.sync.aligned.m8n8.x4.shared.b16 {%0,%1,%2,%3}, [%4];" \
        : "=r"(r0), "=r"(r1), "=r"(r2), "=r"(r3) : "r"(addr))
#define LDSM4T(r0,r1,r2,r3,addr) \
    asm volatile("ldmatrix.sync.aligned.m8n8.x4.trans.shared.b16 {%0,%1,%2,%3}, [%4];" \
        : "=r"(r0), "=r"(r1), "=r"(r2), "=r"(r3) : "r"(addr))
static __device__ __forceinline__ void mma16816(float* c, const uint32_t* a, const uint32_t* b) {
    asm volatile("mma.sync.aligned.m16n8k16.row.col.f32.bf16.bf16.f32 "
        "{%0,%1,%2,%3}, {%4,%5,%6,%7}, {%8,%9}, {%0,%1,%2,%3};"
        : "+f"(c[0]), "+f"(c[1]), "+f"(c[2]), "+f"(c[3])
        : "r"(a[0]), "r"(a[1]), "r"(a[2]), "r"(a[3]), "r"(b[0]), "r"(b[1]));
}
// stage [128 rows x 64 f32] -> bf16 hi/lo, row stride 144B
static __device__ __forceinline__ void stage64(const float* g, char* dH, char* dL, int tid) {
    const float4* g4 = (const float4*)g;
    #pragma unroll
    for (int i = 0; i < 8; ++i) {
        int idx = tid + i * NT;
        int row = idx >> 4, c4 = idx & 15;
        float4 v = g4[idx];
        uint32_t h0, l0, h1, l1;
        pack2(v.x, v.y, h0, l0); pack2(v.z, v.w, h1, l1);
        int off = row * 144 + c4 * 8;
        *(uint2*)(dH + off) = make_uint2(h0, h1);
        *(uint2*)(dL + off) = make_uint2(l0, l1);
    }
}

// ================= Kernel 1: S=QK^T, mask, exp -> attn (unnormalized), Z -> zbuf ==============
__global__ __launch_bounds__(NT, 2)
void sdpa_k1(const float* __restrict__ q, const float* __restrict__ k,
             const int* __restrict__ mask, float* __restrict__ attnp)
{
    extern __shared__ char sm[];
    const int tid = threadIdx.x, lane = tid & 31, w = tid >> 5;
    const int mg = w & 3, ng = w >> 2;            // 4 row-groups x 2 key-groups
    const int bh = blockIdx.x, qt = blockIdx.y;
    const int b = bh >> 4, q0 = qt * 128;
    float* Zs = (float*)(sm + K1_ZS);

    const float* qb = q + ((size_t)bh * S_LEN + q0) * DD;
    const float* kb = k + (size_t)bh * S_LEN * DD;
    const int*   mb = mask + (size_t)b * S_LEN * S_LEN;

    stage64(qb, sm + K1_QHI, sm + K1_QLO, tid);
    if (tid < 128) Zs[tid] = 0.f;

    const uint32_t qhi = s2u(sm + K1_QHI), qlo = s2u(sm + K1_QLO);
    const uint32_t khi = s2u(sm + K1_KHI), klo = s2u(sm + K1_KLO);
    // ldmatrix lane-addr components
    const int arow = (lane & 7) + ((lane >> 3) & 1) * 8;   // row-in-tile (A, 16 rows)
    const int acol = (lane >> 4) * 16;                     // 16B col select
    const int brow = (lane & 7) + ((lane >> 4) << 3);      // B: key row
    const int bcol = ((lane >> 3) & 1) * 16;

    float zacc[2][2] = {{0.f, 0.f}, {0.f, 0.f}};

    for (int ch = 0; ch < NCH; ++ch) {
        __syncthreads();
        stage64(kb + (size_t)ch * CKK * DD, sm + K1_KHI, sm + K1_KLO, tid);
        __syncthreads();

        float creg[2][8][4];
        #pragma unroll
        for (int mt = 0; mt < 2; ++mt)
            #pragma unroll
            for (int nt = 0; nt < 8; ++nt)
                #pragma unroll
                for (int j = 0; j < 4; ++j) creg[mt][nt][j] = 0.f;

        #pragma unroll
        for (int ks = 0; ks < 4; ++ks) {
            uint32_t aH[2][4], aL[2][4];
            #pragma unroll
            for (int mt = 0; mt < 2; ++mt) {
                uint32_t ra = (uint32_t)((mg * 32 + mt * 16 + arow) * 144 + acol + ks * 32);
                LDSM4(aH[mt][0], aH[mt][1], aH[mt][2], aH[mt][3], qhi + ra);
                LDSM4(aL[mt][0], aL[mt][1], aL[mt][2], aL[mt][3], qlo + ra);
            }
            #pragma unroll
            for (int ntp = 0; ntp < 4; ++ntp) {
                int n0 = ng * 64 + ntp * 16;
                uint32_t rb = (uint32_t)((n0 + brow) * 144 + bcol + ks * 32);
                uint32_t bH[4], bL[4];
                LDSM4(bH[0], bH[1], bH[2], bH[3], khi + rb);
                LDSM4(bL[0], bL[1], bL[2], bL[3], klo + rb);
                #pragma unroll
                for (int mt = 0; mt < 2; ++mt) {
                    mma16816(creg[mt][ntp*2],   aH[mt], bH);
                    mma16816(creg[mt][ntp*2],   aH[mt], bL);
                    mma16816(creg[mt][ntp*2],   aL[mt], bH);
                    mma16816(creg[mt][ntp*2+1], aH[mt], bH + 2);
                    mma16816(creg[mt][ntp*2+1], aH[mt], bL + 2);
                    mma16816(creg[mt][ntp*2+1], aL[mt], bH + 2);
                }
            }
        }
        // epilogue: mask + exp, store unnormalized, accumulate Z
        #pragma unroll
        for (int mt = 0; mt < 2; ++mt) {
            int R0 = mg * 32 + mt * 16 + (lane >> 2);
            #pragma unroll
            for (int nt = 0; nt < 8; ++nt) {
                int gc = ch * CKK + ng * 64 + nt * 8 + (lane & 3) * 2;
                int2 m01 = *(const int2*)(mb + (size_t)(q0 + R0) * S_LEN + gc);
                int2 m23 = *(const int2*)(mb + (size_t)(q0 + R0 + 8) * S_LEN + gc);
                float* c = creg[mt][nt];
                float e0 = m01.x ? fexp(c[0] * 0.125f) : 0.f;
                float e1 = m01.y ? fexp(c[1] * 0.125f) : 0.f;
                float e2 = m23.x ? fexp(c[2] * 0.125f) : 0.f;
                float e3 = m23.y ? fexp(c[3] * 0.125f) : 0.f;
                zacc[mt][0] += e0 + e1;
                zacc[mt][1] += e2 + e3;
                float* a0 = attnp + ((size_t)bh * S_LEN + q0 + R0) * S_LEN + gc;
                float* a1 = attnp + ((size_t)bh * S_LEN + q0 + R0 + 8) * S_LEN + gc;
                __stcs((float2*)a0, make_float2(e0, e1));
                __stcs((float2*)a1, make_float2(e2, e3));
            }
        }
    }
    // Z: reduce over 4 lanes sharing a row, then atomic into smem
    #pragma unroll
    for (int mt = 0; mt < 2; ++mt)
        #pragma unroll
        for (int h = 0; h < 2; ++h) {
            float z = zacc[mt][h];
            z += __shfl_xor_sync(0xffffffffu, z, 1);
            z += __shfl_xor_sync(0xffffffffu, z, 2);
            if ((lane & 3) == 0)
                atomicAdd(&Zs[mg * 32 + mt * 16 + (lane >> 2) + 8 * h], z);
        }
    __syncthreads();
    if (tid < 128) zbuf_g[((size_t)bh * 16 + qt) * 128 + tid] = Zs[tid];
}

// ============ Kernel 2: normalize attn, P bf16 -> PV via HMMA, write O ============
__global__ __launch_bounds__(NT, 2)
void sdpa_k2(const float* __restrict__ v, float* __restrict__ attnp,
             float* __restrict__ outp)
{
    extern __shared__ char sm[];
    const int tid = threadIdx.x, lane = tid & 31, w = tid >> 5;
    const int mg = w & 3, ng = w >> 2;            // 4 row-groups x 2 dim-groups
    const int bh = blockIdx.x, qt = blockIdx.y;
    const int q0 = qt * 128;
    float* IZ = (float*)(sm + K2_IZ);

    const float* vb = v + (size_t)bh * S_LEN * DD;
    float* attnb = attnp + ((size_t)bh * S_LEN + q0) * S_LEN;

    if (tid < 128) {
        float z = zbuf_g[((size_t)bh * 16 + qt) * 128 + tid];
        IZ[tid] = (z > 0.f) ? (1.f / z) : 0.f;
    }
    __syncthreads();

    const uint32_t phi = s2u(sm + K2_PHI), plo = s2u(sm + K2_PLO);
    const uint32_t vhi = s2u(sm + K2_VHI), vlo = s2u(sm + K2_VLO);
    const int arow = (lane & 7) + ((lane >> 3) & 1) * 8;
    const int acol = (lane >> 4) * 16;
    const int vrow = (lane & 7) + ((lane >> 3) & 1) * 8;   // key row for V trans
    const int vcol = (lane >> 4) * 8;                      // dim offset (elems)

    float oacc[2][4][4];
    #pragma unroll
    for (int mt = 0; mt < 2; ++mt)
        #pragma unroll
        for (int nt = 0; nt < 4; ++nt)
            #pragma unroll
            for (int j = 0; j < 4; ++j) oacc[mt][nt][j] = 0.f;

    for (int ch = 0; ch < NCH; ++ch) {
        __syncthreads();
        stage64(vb + (size_t)ch * CKK * DD, sm + K2_VHI, sm + K2_VLO, tid);
        // normalize P: read exp fp32, scale, write attn, stage bf16 hi/lo
        {
            const int row = w + 0;  // per-warp constant rows: row = w + i*8
            #pragma unroll
            for (int i = 0; i < 16; ++i) {
                int idx = tid + i * NT;
                int r = idx >> 5, c4 = idx & 31;
                float* gp = attnb + (size_t)r * S_LEN + ch * CKK + c4 * 4;
                float4 e = *(const float4*)gp;
                float iz = IZ[r];
                e.x *= iz; e.y *= iz; e.z *= iz; e.w *= iz;
                __stcs((float4*)gp, e);
                uint32_t h0, l0, h1, l1;
                pack2(e.x, e.y, h0, l0); pack2(e.z, e.w, h1, l1);
                int off = r * 272 + c4 * 8;
                *(uint2*)(sm + K2_PHI + off) = make_uint2(h0, h1);
                *(uint2*)(sm + K2_PLO + off) = make_uint2(l0, l1);
            }
            (void)row;
        }
        __syncthreads();

        #pragma unroll
        for (int ks = 0; ks < 8; ++ks) {
            uint32_t aH[2][4], aL[2][4];
            #pragma unroll
            for (int mt = 0; mt < 2; ++mt) {
                uint32_t ra = (uint32_t)((mg * 32 + mt * 16 + arow) * 272 + acol + ks * 32);
                LDSM4(aH[mt][0], aH[mt][1], aH[mt][2], aH[mt][3], phi + ra);
                LDSM4(aL[mt][0], aL[mt][1], aL[mt][2], aL[mt][3], plo + ra);
            }
            #pragma unroll
            for (int dt = 0; dt < 2; ++dt) {
                int d0 = ng * 32 + dt * 16;
                uint32_t rb = (uint32_t)((ks * 16 + vrow) * 144 + (d0 + vcol) * 2);
                uint32_t bH[4], bL[4];
                LDSM4T(bH[0], bH[1], bH[2], bH[3], vhi + rb);
                LDSM4T(bL[0], bL[1], bL[2], bL[3], vlo + rb);
                #pragma unroll
                for (int mt = 0; mt < 2; ++mt) {
                    mma16816(oacc[mt][dt*2],   aH[mt], bH);
                    mma16816(oacc[mt][dt*2],   aH[mt], bL);
                    mma16816(oacc[mt][dt*2],   aL[mt], bH);
                    mma16816(oacc[mt][dt*2+1], aH[mt], bH + 2);
                    mma16816(oacc[mt][dt*2+1], aH[mt], bL + 2);
                    mma16816(oacc[mt][dt*2+1], aL[mt], bH + 2);
                }
            }
        }
    }
    // write O
    #pragma unroll
    for (int mt = 0; mt < 2; ++mt) {
        int R0 = mg * 32 + mt * 16 + (lane >> 2);
        #pragma unroll
        for (int nt = 0; nt < 4; ++nt) {
            int dc = ng * 32 + nt * 8 + (lane & 3) * 2;
            float* c = oacc[mt][nt];
            float* o0 = outp + ((size_t)bh * S_LEN + q0 + R0) * DD + dc;
            float* o1 = outp + ((size_t)bh * S_LEN + q0 + R0 + 8) * DD + dc;
            *(float2*)o0 = make_float2(c[0], c[1]);
            *(float2*)o1 = make_float2(c[2], c[3]);
        }
    }
}

extern "C" void kernel_launch(void* const* d_in, const int* in_sizes, int n_in,
                              void* d_out, int out_size)
{
    const float* q    = (const float*)d_in[0];
    const float* k    = (const float*)d_in[1];
    const float* v    = (const float*)d_in[2];
    const int*   mask = (const int*)d_in[3];

    float* outp  = (float*)d_out;
    float* attnp = outp + (size_t)2 * 16 * 2048 * 64;

    static bool attrs_set = false;
    cudaFuncSetAttribute(sdpa_k1, cudaFuncAttributeMaxDynamicSharedMemorySize, K1_SMEM);
    cudaFuncSetAttribute(sdpa_k2, cudaFuncAttributeMaxDynamicSharedMemorySize, K2_SMEM);
    (void)attrs_set;

    dim3 grid(32, 16);
    sdpa_k1<<<grid, NT, K1_SMEM>>>(q, k, mask, attnp);
    sdpa_k2<<<grid, NT, K2_SMEM>>>(v, attnp, outp);
}